// round 14
// baseline (speedup 1.0000x reference)
#include <cuda_runtime.h>
#include <math.h>

#define QN   75
#define WAYN 5
#define BTOT (QN*WAYN)    // 375
#define CIN  640
#define CF   64
#define P    100

typedef unsigned long long ull;

// ---------------- scratch (device globals; no allocation APIs) ----------------
__device__ float g_meanC[80*P];              // channel mean per (b, p); b: 0..4 spt, 5..79 qry
__device__ float g_feat[80*CF*P];            // normalized 64-ch features
__device__ float g_corr[BTOT*P*P];           // corr[b][ps][pq]
__device__ float g_corrT[BTOT*P*P];          // corr[b][pq][ps]
__device__ float g_t2[2][BTOT*P*P];          // after stages A+B, per branch
__device__ float g_cca1[BTOT*P*P];           // branch 1 output [ps][pq]
__device__ float g_cca2[BTOT*P*P];           // branch 2 output, already transposed back to [ps][pq]
__device__ float g_as[BTOT*P];
__device__ float g_aq[BTOT*P];
__device__ ull   g_wDp[2304];                // packed f32x2 (both halves equal) c2 conv2 weights
__device__ ull   g_wEFp[144];                // packed folded EF weights [tap][i]

struct Consts {
    float wsum[64];
    float s1[64], b1[64];        // bn_1x1 affine
    float wA[9],  bA;            // c1 conv2(uv) * bn2
    float wB[9],  bB;            // c1 conv1(hw) * bn1
    float aC[16], cC[16];        // c1 proj+bnp folded: r_j = relu(aC*t2 + cC)
    float tD[16];                // c2 bn2 shift (relu after)
    float bEF;                   // folded conv1+bn1+proj+bnp bias
};
__device__ Consts g_c;

__device__ __forceinline__ void bn_affine(const float* p, int C, int c, float& s, float& sh) {
    float g = p[c], b = p[C + c], m = p[2*C + c], v = p[3*C + c];
    s  = g * rsqrtf(v + 1e-5f);
    sh = b - m * s;
}

// ---------------- f32x2 helpers (Blackwell packed fp32) ----------------
__device__ __forceinline__ ull ffma2(ull a, ull b, ull c) {
    ull d;
    asm("fma.rn.f32x2 %0, %1, %2, %3;" : "=l"(d) : "l"(a), "l"(b), "l"(c));
    return d;
}
__device__ __forceinline__ ull pk2(float lo, float hi) {
    ull r;
    asm("mov.b64 %0, {%1, %2};" : "=l"(r) : "f"(lo), "f"(hi));
    return r;
}
__device__ __forceinline__ void up2(ull v, float& lo, float& hi) {
    asm("mov.b64 {%0, %1}, %2;" : "=f"(lo), "=f"(hi) : "l"(v));
}
__device__ __forceinline__ ull bcast2(float w) {
    unsigned u = __float_as_uint(w);
    return ((ull)u << 32) | (ull)u;
}

// ---------------- prep: fold all BN affines / projections into weights ----------------
__global__ void __launch_bounds__(256) prep_kernel(
        const float* __restrict__ w1x1, const float* __restrict__ bn1x1,
        const float* __restrict__ c1w2, const float* __restrict__ c1b2,
        const float* __restrict__ c1w1, const float* __restrict__ c1b1,
        const float* __restrict__ c1pw, const float* __restrict__ c1bp,
        const float* __restrict__ c2w2, const float* __restrict__ c2b2,
        const float* __restrict__ c2w1, const float* __restrict__ c2b1,
        const float* __restrict__ c2pw, const float* __restrict__ c2bp) {
    int t = threadIdx.x;
    if (t < 64) {
        float s = 0.f;
        for (int c = 0; c < CIN; c++) s += w1x1[t*CIN + c];
        g_c.wsum[t] = s;
        bn_affine(bn1x1, 64, t, g_c.s1[t], g_c.b1[t]);
    }
    if (t == 0) {
        float sA, shA; bn_affine(c1b2, 1, 0, sA, shA);
        for (int k = 0; k < 9; k++) g_c.wA[k] = c1w2[k] * sA;
        g_c.bA = shA;
        float sB, shB; bn_affine(c1b1, 1, 0, sB, shB);
        for (int k = 0; k < 9; k++) g_c.wB[k] = c1w1[k] * sB;
        g_c.bB = shB;
        float sF, shF; bn_affine(c2bp, 1, 0, sF, shF);
        float acc = 0.f;
        for (int o = 0; o < 16; o++) {
            float sE, shE; bn_affine(c2b1, 16, o, sE, shE);
            acc += c2pw[o] * shE;
        }
        g_c.bEF = sF * acc + shF;
    }
    if (t < 16) {
        float sP, shP; bn_affine(c1bp, 16, t, sP, shP);
        g_c.aC[t] = c1pw[t] * sP;
        g_c.cC[t] = shP;
        float sD, shD; bn_affine(c2b2, 16, t, sD, shD);
        g_c.tD[t] = shD;
    }
    // wDp[(o*16+j)*9+tap] = pack2(c2w2 * sD[o])
    for (int i = t; i < 2304; i += blockDim.x) {
        int o = i / 144;
        float sD, shD; bn_affine(c2b2, 16, o, sD, shD);
        g_wDp[i] = bcast2(c2w2[i] * sD);
    }
    // wEFp[tap*16+i] = pack2( sF * sum_o pw[o]*sE[o]*c2w1[(o*16+i)*9+tap] )
    for (int i = t; i < 144; i += blockDim.x) {
        int tap = i / 16, j = i % 16;
        float sF, shF; bn_affine(c2bp, 1, 0, sF, shF);
        float acc = 0.f;
        for (int o = 0; o < 16; o++) {
            float sE, shE; bn_affine(c2b1, 16, o, sE, shE);
            acc += c2pw[o] * sE * c2w1[(o*16 + j)*9 + tap];
        }
        g_wEFp[i] = bcast2(sF * acc);
    }
}

// ---------------- 1x1 conv (640->64) + bn + relu + L2-norm; also produces g_meanC ----------------
__global__ void __launch_bounds__(256) feat_kernel(
        const float* __restrict__ spt, const float* __restrict__ qry,
        const float* __restrict__ w1x1) {
    __shared__ float sm[6400 + 64*65 + 64];   // xs[64][100] | ws[64][65]; reused as yb[64][101]+nrm
    __shared__ float mC[100];
    float* xs = sm;
    float* ws = sm + 6400;
    int b = blockIdx.x, t = threadIdx.x;
    const float* xb = (b < WAYN) ? (spt + (size_t)b*CIN*P) : (qry + (size_t)(b - WAYN)*CIN*P);
    int o = t & 63, pb = t >> 6;       // thread owns (o, p = pb + 4j)
    float acc[25];
    #pragma unroll
    for (int j = 0; j < 25; j++) acc[j] = 0.f;
    float msum = 0.f;                  // channel-sum for p = t (threads t < 100)

    for (int c0 = 0; c0 < CIN; c0 += 64) {
        __syncthreads();
        for (int i = t; i < 6400; i += 256) {
            int cc = i / 100, p = i % 100;
            xs[i] = xb[(c0 + cc)*P + p];
        }
        for (int i = t; i < 4096; i += 256) {
            int oo = i >> 6, cc = i & 63;
            ws[oo*65 + cc] = w1x1[oo*CIN + c0 + cc];
        }
        __syncthreads();
        if (t < 100) {
            #pragma unroll 8
            for (int cc = 0; cc < 64; cc++) msum += xs[cc*100 + t];
        }
        #pragma unroll 4
        for (int cc = 0; cc < 64; cc++) {
            float wv = ws[o*65 + cc];
            const float* xr = xs + cc*100 + pb;
            #pragma unroll
            for (int j = 0; j < 25; j++) acc[j] = fmaf(wv, xr[4*j], acc[j]);
        }
    }
    if (t < 100) {
        float m = msum * (1.f/CIN);
        mC[t] = m;
        g_meanC[b*P + t] = m;
    }
    __syncthreads();
    float* yb  = sm;                 // [64][101]
    float* nrm = sm + 64*101;        // [100]
    float wsum = g_c.wsum[o], s1 = g_c.s1[o], b1 = g_c.b1[o];
    float mCr[25];
    #pragma unroll
    for (int j = 0; j < 25; j++) mCr[j] = mC[pb + 4*j];
    __syncthreads();                 // all xs reads done before yb overwrites sm
    #pragma unroll
    for (int j = 0; j < 25; j++) {
        int p = pb + 4*j;
        float v = acc[j] - mCr[j]*wsum;
        v = fmaf(s1, v, b1);
        yb[o*101 + p] = fmaxf(v, 0.f);
    }
    __syncthreads();
    if (t < 100) {
        float s = 0.f;
        for (int oo = 0; oo < 64; oo++) { float v = yb[oo*101 + t]; s = fmaf(v, v, s); }
        nrm[t] = fmaxf(sqrtf(s), 1e-8f);
    }
    __syncthreads();
    for (int i = t; i < 6400; i += 256) {
        int oo = i / 100, p = i % 100;
        g_feat[b*6400 + i] = yb[oo*101 + p] / nrm[p];
    }
}

// ---------------- corr[b][ps][pq] = sum_o sf[o][ps]*qf[o][pq]; also write transpose ----------------
__global__ void __launch_bounds__(256) corr_kernel() {
    __shared__ float sfs[3200];
    __shared__ float qfs[3200];
    int b = blockIdx.x;
    int qi = b / WAYN, n = b % WAYN;
    int t = threadIdx.x;
    float acc[40];
    #pragma unroll
    for (int r = 0; r < 40; r++) acc[r] = 0.f;
    for (int h = 0; h < 2; h++) {
        __syncthreads();
        for (int i = t; i < 3200; i += 256) {
            sfs[i] = g_feat[n*6400 + h*3200 + i];
            qfs[i] = g_feat[(WAYN + qi)*6400 + h*3200 + i];
        }
        __syncthreads();
        #pragma unroll
        for (int r = 0; r < 40; r++) {
            int idx = t + r*256;
            if (idx < 10000) {
                int ps = idx / 100, pq = idx % 100;
                float a = acc[r];
                #pragma unroll 8
                for (int oo = 0; oo < 32; oo++)
                    a = fmaf(sfs[oo*100 + ps], qfs[oo*100 + pq], a);
                acc[r] = a;
            }
        }
    }
    for (int r = 0; r < 40; r++) {
        int idx = t + r*256;
        if (idx < 10000) {
            int ps = idx / 100, pq = idx % 100;
            g_corr[b*10000 + idx] = acc[r];
            g_corrT[b*10000 + pq*100 + ps] = acc[r];
        }
    }
}

// ---------------- fused stages A+B: conv(uv)+relu then conv(hw), register ping ----------------
// grid = (BTOT, 2): blockIdx.y = branch mode
__global__ void __launch_bounds__(256) stageAB_kernel() {
    __shared__ float s_in[10000];
    int b = blockIdx.x, mode = blockIdx.y, t = threadIdx.x;
    const float* __restrict__ in = mode ? g_corrT : g_corr;
    for (int i = t; i < 10000; i += 256) s_in[i] = in[b*10000 + i];
    __syncthreads();
    float wA[9], wB[9];
    #pragma unroll
    for (int k = 0; k < 9; k++) { wA[k] = g_c.wA[k]; wB[k] = g_c.wB[k]; }
    float bA = g_c.bA, bB = g_c.bB;

    // stage A into registers
    float r[40];
    #pragma unroll
    for (int rr = 0; rr < 40; rr++) {
        int i = t + rr*256;
        if (i >= 10000) continue;
        int uv = i / 100, hw = i % 100, u = uv / 10, v = uv % 10;
        float a = bA;
        #pragma unroll
        for (int ku = 0; ku < 3; ku++) {
            int u2 = u + ku - 1;
            if (u2 < 0 || u2 >= 10) continue;
            #pragma unroll
            for (int kv = 0; kv < 3; kv++) {
                int v2 = v + kv - 1;
                if (v2 < 0 || v2 >= 10) continue;
                a = fmaf(wA[ku*3 + kv], s_in[(u2*10 + v2)*100 + hw], a);
            }
        }
        r[rr] = fmaxf(a, 0.f);
    }
    __syncthreads();
    #pragma unroll
    for (int rr = 0; rr < 40; rr++) {
        int i = t + rr*256;
        if (i < 10000) s_in[i] = r[rr];
    }
    __syncthreads();

    // stage B from smem -> g_t2[mode]
    float* __restrict__ t2o = g_t2[mode] + (size_t)b*10000;
    for (int i = t; i < 10000; i += 256) {
        int uv = i / 100, hw = i % 100, h = hw / 10, w = hw % 10;
        float a = bB;
        #pragma unroll
        for (int kh = 0; kh < 3; kh++) {
            int h2 = h + kh - 1;
            if (h2 < 0 || h2 >= 10) continue;
            #pragma unroll
            for (int kw = 0; kw < 3; kw++) {
                int w2 = w + kw - 1;
                if (w2 < 0 || w2 >= 10) continue;
                a = fmaf(wB[kh*3 + kw], s_in[uv*100 + h2*10 + w2], a);
            }
        }
        t2o[i] = a;
    }
}

// ---------------- fused stage D+EF ----------------
// D: per point, 16 channels r_j = relu(aC_j*t2 + cC_j); y_o = relu(sum_{tap,j} wD * r_j + tD_o)
//    (3x3 conv over uv, reads t2 neighbors from global/L2)
// EF: folded 16->1 3x3 conv over (h,w), scattered into shared accumulator.
// grid = (5, BTOT, 2): uv fifth (20 uv), b, branch mode. 500 tiles/block over 256 threads
// -> max 2 iterations/thread (98% tile-slot utilization).
// f32x2 packed math, 4-pt x 16-out tile.
// mode 0 writes g_cca1[b][ps][pq]; mode 1 writes g_cca2[b][ps][pq] (transposed back, plain store).
__global__ void __launch_bounds__(256) stageDEF_kernel() {
    __shared__ float accs[2000];
    __shared__ ull wDs[2304];
    __shared__ ull wEFs[144];
    __shared__ float aCs[16], cCs[16], tDs[16];
    int qu = blockIdx.x, b = blockIdx.y, mode = blockIdx.z, t = threadIdx.x;
    for (int i = t; i < 2000; i += 256) accs[i] = 0.f;
    for (int i = t; i < 2304; i += 256) wDs[i] = g_wDp[i];
    if (t < 144) wEFs[t] = g_wEFp[t];
    if (t < 16) { aCs[t] = g_c.aC[t]; cCs[t] = g_c.cC[t]; tDs[t] = g_c.tD[t]; }
    __syncthreads();
    float aCr[16], cCr[16], tDr[16];
    #pragma unroll
    for (int j = 0; j < 16; j++) { aCr[j] = aCs[j]; cCr[j] = cCs[j]; tDr[j] = tDs[j]; }
    const float* __restrict__ t2b = g_t2[mode] + (size_t)b*10000;

    for (int tile = t; tile < 500; tile += 256) {
        int luv = tile / 25;            // 0..19 within fifth
        int hw0 = (tile % 25) * 4;      // 4 consecutive hw points
        int uv  = qu*20 + luv;
        int u = uv / 10, v = uv % 10;

        ull a01[16], a23[16];
        #pragma unroll
        for (int o = 0; o < 16; o++) { a01[o] = 0ull; a23[o] = 0ull; }

        #pragma unroll 1
        for (int tap = 0; tap < 9; tap++) {
            int ua = u + tap/3 - 1, va = v + tap%3 - 1;
            if (ua < 0 || ua >= 10 || va < 0 || va >= 10) continue;  // zero-padded t3
            float4 x4 = *(const float4*)(t2b + (ua*10 + va)*100 + hw0);
            const ull* wt = wDs + tap;
            #pragma unroll
            for (int j = 0; j < 16; j++) {
                float r0 = fmaxf(fmaf(aCr[j], x4.x, cCr[j]), 0.f);
                float r1 = fmaxf(fmaf(aCr[j], x4.y, cCr[j]), 0.f);
                float r2 = fmaxf(fmaf(aCr[j], x4.z, cCr[j]), 0.f);
                float r3 = fmaxf(fmaf(aCr[j], x4.w, cCr[j]), 0.f);
                ull r01 = pk2(r0, r1), r23 = pk2(r2, r3);
                #pragma unroll
                for (int o = 0; o < 16; o++) {
                    ull w = wt[(o*16 + j)*9];
                    a01[o] = ffma2(w, r01, a01[o]);
                    a23[o] = ffma2(w, r23, a23[o]);
                }
            }
        }

        // EF: t4_o = relu(acc_o + tD_o); sc[tap] = sum_o wEF[tap][o] * t4_o
        ull sc01[9], sc23[9];
        #pragma unroll
        for (int k = 0; k < 9; k++) { sc01[k] = 0ull; sc23[k] = 0ull; }
        #pragma unroll
        for (int o = 0; o < 16; o++) {
            float p0, p1, p2, p3;
            up2(a01[o], p0, p1); up2(a23[o], p2, p3);
            p0 = fmaxf(p0 + tDr[o], 0.f);
            p1 = fmaxf(p1 + tDr[o], 0.f);
            p2 = fmaxf(p2 + tDr[o], 0.f);
            p3 = fmaxf(p3 + tDr[o], 0.f);
            ull t01 = pk2(p0, p1), t23 = pk2(p2, p3);
            #pragma unroll
            for (int k = 0; k < 9; k++) {
                ull w = wEFs[k*16 + o];
                sc01[k] = ffma2(w, t01, sc01[k]);
                sc23[k] = ffma2(w, t23, sc23[k]);
            }
        }
        // scatter: t4 at (h,w) with tap (kh,kw) contributes to output (h+1-kh, w+1-kw)
        #pragma unroll 1
        for (int k = 0; k < 9; k++) {
            int dh = 1 - k/3, dw = 1 - k%3;
            float s0, s1, s2, s3;
            up2(sc01[k], s0, s1); up2(sc23[k], s2, s3);
            float sv[4] = {s0, s1, s2, s3};
            #pragma unroll
            for (int p = 0; p < 4; p++) {
                int hw = hw0 + p;
                int h2 = hw/10 + dh, w2 = hw%10 + dw;
                if (h2 >= 0 && h2 < 10 && w2 >= 0 && w2 < 10)
                    atomicAdd(&accs[luv*100 + h2*10 + w2], sv[p]);
            }
        }
    }
    __syncthreads();
    float bEF = g_c.bEF;
    if (mode == 0) {
        for (int i = t; i < 2000; i += 256)
            g_cca1[(size_t)b*10000 + qu*2000 + i] = accs[i] + bEF;
    } else {
        for (int i = t; i < 2000; i += 256) {
            int luv = i / 100, hw = i % 100;
            int uv = qu*20 + luv;
            g_cca2[(size_t)b*10000 + hw*100 + uv] = accs[i] + bEF;  // plain transposed store
        }
    }
}

// ---------------- gaussian-normalize (ddof=1) + softmax(T=5) + sums ----------------
__global__ void __launch_bounds__(128) attn_kernel() {
    __shared__ float s[10000];
    __shared__ float cmean[100], cinv[100], cmax[100], cZi[100];
    __shared__ float rmean[100], rinv[100], rmax[100], rZi[100];
    int b = blockIdx.x, t = threadIdx.x;
    for (int i = t; i < 10000; i += 128)
        s[i] = g_cca1[(size_t)b*10000 + i] + g_cca2[(size_t)b*10000 + i];
    __syncthreads();
    if (t < 100) {
        float sum = 0.f, sq = 0.f, mx = -1e30f;
        for (int ps = 0; ps < 100; ps++) {
            float v = s[ps*100 + t];
            sum += v; sq = fmaf(v, v, sq); mx = fmaxf(mx, v);
        }
        float mean = sum * 0.01f;
        float var  = (sq - sum*mean) * (1.f/99.f);
        float inv  = rsqrtf(var + 1e-5f) * 0.2f;   // includes 1/TEMPERATURE_ATTN
        float Lm   = (mx - mean) * inv;
        float Z = 0.f;
        for (int ps = 0; ps < 100; ps++)
            Z += expf((s[ps*100 + t] - mean)*inv - Lm);
        cmean[t] = mean; cinv[t] = inv; cmax[t] = Lm; cZi[t] = 1.f/Z;

        sum = 0.f; sq = 0.f; mx = -1e30f;
        for (int pq = 0; pq < 100; pq++) {
            float v = s[t*100 + pq];
            sum += v; sq = fmaf(v, v, sq); mx = fmaxf(mx, v);
        }
        mean = sum * 0.01f;
        var  = (sq - sum*mean) * (1.f/99.f);
        inv  = rsqrtf(var + 1e-5f) * 0.2f;
        Lm   = (mx - mean) * inv;
        Z = 0.f;
        for (int pq = 0; pq < 100; pq++)
            Z += expf((s[t*100 + pq] - mean)*inv - Lm);
        rmean[t] = mean; rinv[t] = inv; rmax[t] = Lm; rZi[t] = 1.f/Z;
    }
    __syncthreads();
    if (t < 100) {
        float a = 0.f;
        for (int pq = 0; pq < 100; pq++) {
            float v = s[t*100 + pq];
            a += expf((v - cmean[pq])*cinv[pq] - cmax[pq]) * cZi[pq];
        }
        g_as[b*100 + t] = a;
        float q = 0.f;
        for (int ps = 0; ps < 100; ps++) {
            float v = s[ps*100 + t];
            q += expf((v - rmean[ps])*rinv[ps] - rmax[ps]) * rZi[ps];
        }
        g_aq[b*100 + t] = q;
    }
}

// ---------------- attended pooling + cosine sim ----------------
__global__ void __launch_bounds__(256) final_kernel(
        const float* __restrict__ spt, const float* __restrict__ qry,
        float* __restrict__ out) {
    __shared__ float as[100], aq[100];
    __shared__ float red[256];
    int b = blockIdx.x;
    int qi = b / WAYN, n = b % WAYN;
    int t = threadIdx.x;
    if (t < 100) { as[t] = g_as[b*100 + t]; aq[t] = g_aq[b*100 + t]; }
    __syncthreads();
    float pr = (t < 100) ? as[t]*g_meanC[n*100 + t] : 0.f;
    red[t] = pr; __syncthreads();
    for (int st = 128; st > 0; st >>= 1) { if (t < st) red[t] += red[t + st]; __syncthreads(); }
    float dot_s = red[0]; __syncthreads();
    pr = (t < 100) ? aq[t]*g_meanC[(WAYN + qi)*100 + t] : 0.f;
    red[t] = pr; __syncthreads();
    for (int st = 128; st > 0; st >>= 1) { if (t < st) red[t] += red[t + st]; __syncthreads(); }
    float dot_q = red[0]; __syncthreads();

    float num = 0.f, ss = 0.f, qq = 0.f;
    const float* sp = spt + (size_t)n*CIN*P;
    const float* qp = qry + (size_t)qi*CIN*P;
    for (int c = t; c < CIN; c += 256) {
        const float* srow = sp + c*P;
        const float* qrow = qp + c*P;
        float sa = 0.f, qa = 0.f;
        for (int p = 0; p < P; p++) {
            sa = fmaf(as[p], srow[p], sa);
            qa = fmaf(aq[p], qrow[p], qa);
        }
        sa = (sa - dot_s) * 0.01f;
        qa = (qa - dot_q) * 0.01f;
        num = fmaf(sa, qa, num);
        ss  = fmaf(sa, sa, ss);
        qq  = fmaf(qa, qa, qq);
    }
    red[t] = num; __syncthreads();
    for (int st = 128; st > 0; st >>= 1) { if (t < st) red[t] += red[t + st]; __syncthreads(); }
    float N = red[0]; __syncthreads();
    red[t] = ss; __syncthreads();
    for (int st = 128; st > 0; st >>= 1) { if (t < st) red[t] += red[t + st]; __syncthreads(); }
    float S = red[0]; __syncthreads();
    red[t] = qq; __syncthreads();
    for (int st = 128; st > 0; st >>= 1) { if (t < st) red[t] += red[t + st]; __syncthreads(); }
    float Qv = red[0];
    if (t == 0) {
        float den = fmaxf(sqrtf(S), 1e-8f) * fmaxf(sqrtf(Qv), 1e-8f);
        out[b] = (N / den) * 5.0f;    // /TEMPERATURE (0.2)
    }
}

// ---------------- qry_pooled ----------------
__global__ void __launch_bounds__(128) pooled_kernel(
        const float* __restrict__ qry, float* __restrict__ out) {
    __shared__ float red[128];
    int q = blockIdx.x, t = threadIdx.x;
    red[t] = (t < 100) ? g_meanC[(WAYN + q)*100 + t] : 0.f;
    __syncthreads();
    for (int st = 64; st > 0; st >>= 1) { if (t < st) red[t] += red[t + st]; __syncthreads(); }
    float mp = red[0] * 0.01f;
    const float* qp = qry + (size_t)q*CIN*P;
    for (int c = t; c < CIN; c += 128) {
        float s = 0.f;
        for (int p = 0; p < P; p++) s += qp[c*P + p];
        out[BTOT + q*CIN + c] = s * 0.01f - mp;
    }
}

// ---------------- launcher ----------------
extern "C" void kernel_launch(void* const* d_in, const int* in_sizes, int n_in,
                              void* d_out, int out_size) {
    const float* spt   = (const float*)d_in[0];
    const float* qry   = (const float*)d_in[1];
    const float* w1x1  = (const float*)d_in[2];
    const float* bn1x1 = (const float*)d_in[3];
    const float* c1w2  = (const float*)d_in[4];
    const float* c1b2  = (const float*)d_in[5];
    const float* c1w1  = (const float*)d_in[6];
    const float* c1b1  = (const float*)d_in[7];
    const float* c1pw  = (const float*)d_in[8];
    const float* c1bp  = (const float*)d_in[9];
    const float* c2w2  = (const float*)d_in[10];
    const float* c2b2  = (const float*)d_in[11];
    const float* c2w1  = (const float*)d_in[12];
    const float* c2b1  = (const float*)d_in[13];
    const float* c2pw  = (const float*)d_in[14];
    const float* c2bp  = (const float*)d_in[15];
    float* out = (float*)d_out;

    prep_kernel<<<1, 256>>>(w1x1, bn1x1, c1w2, c1b2, c1w1, c1b1, c1pw, c1bp,
                            c2w2, c2b2, c2w1, c2b1, c2pw, c2bp);
    feat_kernel<<<80, 256>>>(spt, qry, w1x1);
    corr_kernel<<<BTOT, 256>>>();

    stageAB_kernel<<<dim3(BTOT, 2), 256>>>();
    stageDEF_kernel<<<dim3(5, BTOT, 2), 256>>>();

    attn_kernel<<<BTOT, 128>>>();
    final_kernel<<<BTOT, 256>>>(spt, qry, out);
    pooled_kernel<<<QN, 128>>>(qry, out);
}

// round 15
// speedup vs baseline: 1.0396x; 1.0396x over previous
#include <cuda_runtime.h>
#include <math.h>

#define QN   75
#define WAYN 5
#define BTOT (QN*WAYN)    // 375
#define CIN  640
#define CF   64
#define P    100

typedef unsigned long long ull;

// ---------------- scratch (device globals; no allocation APIs) ----------------
__device__ float g_meanC[80*P];              // channel mean per (b, p); b: 0..4 spt, 5..79 qry
__device__ float g_feat[80*CF*P];            // normalized 64-ch features
__device__ float g_corr[BTOT*P*P];           // corr[b][ps][pq]
__device__ float g_corrT[BTOT*P*P];          // corr[b][pq][ps]
__device__ float g_t2[2][BTOT*P*P];          // after stages A+B, per branch
__device__ float g_cca1[BTOT*P*P];           // branch 1 output [ps][pq]
__device__ float g_cca2[BTOT*P*P];           // branch 2 output, already transposed back to [ps][pq]
__device__ float g_as[BTOT*P];
__device__ float g_aq[BTOT*P];
__device__ ull   g_wDp[2304];                // packed f32x2 (both halves equal) c2 conv2 weights
__device__ ull   g_wEFp[144];                // packed folded EF weights [tap][i]

struct Consts {
    float wsum[64];
    float s1[64], b1[64];        // bn_1x1 affine
    float wA[9],  bA;            // c1 conv2(uv) * bn2
    float wB[9],  bB;            // c1 conv1(hw) * bn1
    float aC[16], cC[16];        // c1 proj+bnp folded: r_j = relu(aC*t2 + cC)
    float tD[16];                // c2 bn2 shift (relu after)
    float bEF;                   // folded conv1+bn1+proj+bnp bias
};
__device__ Consts g_c;

__device__ __forceinline__ void bn_affine(const float* p, int C, int c, float& s, float& sh) {
    float g = p[c], b = p[C + c], m = p[2*C + c], v = p[3*C + c];
    s  = g * rsqrtf(v + 1e-5f);
    sh = b - m * s;
}

// ---------------- f32x2 helpers (Blackwell packed fp32) ----------------
__device__ __forceinline__ ull ffma2(ull a, ull b, ull c) {
    ull d;
    asm("fma.rn.f32x2 %0, %1, %2, %3;" : "=l"(d) : "l"(a), "l"(b), "l"(c));
    return d;
}
__device__ __forceinline__ ull pk2(float lo, float hi) {
    ull r;
    asm("mov.b64 %0, {%1, %2};" : "=l"(r) : "f"(lo), "f"(hi));
    return r;
}
__device__ __forceinline__ void up2(ull v, float& lo, float& hi) {
    asm("mov.b64 {%0, %1}, %2;" : "=f"(lo), "=f"(hi) : "l"(v));
}
__device__ __forceinline__ ull bcast2(float w) {
    unsigned u = __float_as_uint(w);
    return ((ull)u << 32) | (ull)u;
}

// ---------------- prep: fold all BN affines / projections into weights ----------------
__global__ void __launch_bounds__(256) prep_kernel(
        const float* __restrict__ w1x1, const float* __restrict__ bn1x1,
        const float* __restrict__ c1w2, const float* __restrict__ c1b2,
        const float* __restrict__ c1w1, const float* __restrict__ c1b1,
        const float* __restrict__ c1pw, const float* __restrict__ c1bp,
        const float* __restrict__ c2w2, const float* __restrict__ c2b2,
        const float* __restrict__ c2w1, const float* __restrict__ c2b1,
        const float* __restrict__ c2pw, const float* __restrict__ c2bp) {
    int t = threadIdx.x;
    if (t < 64) {
        float s = 0.f;
        for (int c = 0; c < CIN; c++) s += w1x1[t*CIN + c];
        g_c.wsum[t] = s;
        bn_affine(bn1x1, 64, t, g_c.s1[t], g_c.b1[t]);
    }
    if (t == 0) {
        float sA, shA; bn_affine(c1b2, 1, 0, sA, shA);
        for (int k = 0; k < 9; k++) g_c.wA[k] = c1w2[k] * sA;
        g_c.bA = shA;
        float sB, shB; bn_affine(c1b1, 1, 0, sB, shB);
        for (int k = 0; k < 9; k++) g_c.wB[k] = c1w1[k] * sB;
        g_c.bB = shB;
        float sF, shF; bn_affine(c2bp, 1, 0, sF, shF);
        float acc = 0.f;
        for (int o = 0; o < 16; o++) {
            float sE, shE; bn_affine(c2b1, 16, o, sE, shE);
            acc += c2pw[o] * shE;
        }
        g_c.bEF = sF * acc + shF;
    }
    if (t < 16) {
        float sP, shP; bn_affine(c1bp, 16, t, sP, shP);
        g_c.aC[t] = c1pw[t] * sP;
        g_c.cC[t] = shP;
        float sD, shD; bn_affine(c2b2, 16, t, sD, shD);
        g_c.tD[t] = shD;
    }
    // wDp[(o*16+j)*9+tap] = pack2(c2w2 * sD[o])
    for (int i = t; i < 2304; i += blockDim.x) {
        int o = i / 144;
        float sD, shD; bn_affine(c2b2, 16, o, sD, shD);
        g_wDp[i] = bcast2(c2w2[i] * sD);
    }
    // wEFp[tap*16+i] = pack2( sF * sum_o pw[o]*sE[o]*c2w1[(o*16+i)*9+tap] )
    for (int i = t; i < 144; i += blockDim.x) {
        int tap = i / 16, j = i % 16;
        float sF, shF; bn_affine(c2bp, 1, 0, sF, shF);
        float acc = 0.f;
        for (int o = 0; o < 16; o++) {
            float sE, shE; bn_affine(c2b1, 16, o, sE, shE);
            acc += c2pw[o] * sE * c2w1[(o*16 + j)*9 + tap];
        }
        g_wEFp[i] = bcast2(sF * acc);
    }
}

// ---------------- 1x1 conv (640->64) + bn + relu + L2-norm; also produces g_meanC ----------------
__global__ void __launch_bounds__(256) feat_kernel(
        const float* __restrict__ spt, const float* __restrict__ qry,
        const float* __restrict__ w1x1) {
    __shared__ float sm[6400 + 64*65 + 64];   // xs[64][100] | ws[64][65]; reused as yb[64][101]+nrm
    __shared__ float mC[100];
    float* xs = sm;
    float* ws = sm + 6400;
    int b = blockIdx.x, t = threadIdx.x;
    const float* xb = (b < WAYN) ? (spt + (size_t)b*CIN*P) : (qry + (size_t)(b - WAYN)*CIN*P);
    int o = t & 63, pb = t >> 6;       // thread owns (o, p = pb + 4j)
    float acc[25];
    #pragma unroll
    for (int j = 0; j < 25; j++) acc[j] = 0.f;
    float msum = 0.f;                  // channel-sum for p = t (threads t < 100)

    for (int c0 = 0; c0 < CIN; c0 += 64) {
        __syncthreads();
        for (int i = t; i < 6400; i += 256) {
            int cc = i / 100, p = i % 100;
            xs[i] = xb[(c0 + cc)*P + p];
        }
        for (int i = t; i < 4096; i += 256) {
            int oo = i >> 6, cc = i & 63;
            ws[oo*65 + cc] = w1x1[oo*CIN + c0 + cc];
        }
        __syncthreads();
        if (t < 100) {
            #pragma unroll 8
            for (int cc = 0; cc < 64; cc++) msum += xs[cc*100 + t];
        }
        #pragma unroll 4
        for (int cc = 0; cc < 64; cc++) {
            float wv = ws[o*65 + cc];
            const float* xr = xs + cc*100 + pb;
            #pragma unroll
            for (int j = 0; j < 25; j++) acc[j] = fmaf(wv, xr[4*j], acc[j]);
        }
    }
    if (t < 100) {
        float m = msum * (1.f/CIN);
        mC[t] = m;
        g_meanC[b*P + t] = m;
    }
    __syncthreads();
    float* yb  = sm;                 // [64][101]
    float* nrm = sm + 64*101;        // [100]
    float wsum = g_c.wsum[o], s1 = g_c.s1[o], b1 = g_c.b1[o];
    float mCr[25];
    #pragma unroll
    for (int j = 0; j < 25; j++) mCr[j] = mC[pb + 4*j];
    __syncthreads();                 // all xs reads done before yb overwrites sm
    #pragma unroll
    for (int j = 0; j < 25; j++) {
        int p = pb + 4*j;
        float v = acc[j] - mCr[j]*wsum;
        v = fmaf(s1, v, b1);
        yb[o*101 + p] = fmaxf(v, 0.f);
    }
    __syncthreads();
    if (t < 100) {
        float s = 0.f;
        for (int oo = 0; oo < 64; oo++) { float v = yb[oo*101 + t]; s = fmaf(v, v, s); }
        nrm[t] = fmaxf(sqrtf(s), 1e-8f);
    }
    __syncthreads();
    for (int i = t; i < 6400; i += 256) {
        int oo = i / 100, p = i % 100;
        g_feat[b*6400 + i] = yb[oo*101 + p] / nrm[p];
    }
}

// ---------------- corr[b][ps][pq] = sum_o sf[o][ps]*qf[o][pq]; also write transpose ----------------
__global__ void __launch_bounds__(256) corr_kernel() {
    __shared__ float sfs[3200];
    __shared__ float qfs[3200];
    int b = blockIdx.x;
    int qi = b / WAYN, n = b % WAYN;
    int t = threadIdx.x;
    float acc[40];
    #pragma unroll
    for (int r = 0; r < 40; r++) acc[r] = 0.f;
    for (int h = 0; h < 2; h++) {
        __syncthreads();
        for (int i = t; i < 3200; i += 256) {
            sfs[i] = g_feat[n*6400 + h*3200 + i];
            qfs[i] = g_feat[(WAYN + qi)*6400 + h*3200 + i];
        }
        __syncthreads();
        #pragma unroll
        for (int r = 0; r < 40; r++) {
            int idx = t + r*256;
            if (idx < 10000) {
                int ps = idx / 100, pq = idx % 100;
                float a = acc[r];
                #pragma unroll 8
                for (int oo = 0; oo < 32; oo++)
                    a = fmaf(sfs[oo*100 + ps], qfs[oo*100 + pq], a);
                acc[r] = a;
            }
        }
    }
    for (int r = 0; r < 40; r++) {
        int idx = t + r*256;
        if (idx < 10000) {
            int ps = idx / 100, pq = idx % 100;
            g_corr[b*10000 + idx] = acc[r];
            g_corrT[b*10000 + pq*100 + ps] = acc[r];
        }
    }
}

// ---------------- fused stages A+B: conv(uv)+relu then conv(hw), register ping ----------------
// grid = (BTOT, 2): blockIdx.y = branch mode
__global__ void __launch_bounds__(256) stageAB_kernel() {
    __shared__ float s_in[10000];
    int b = blockIdx.x, mode = blockIdx.y, t = threadIdx.x;
    const float* __restrict__ in = mode ? g_corrT : g_corr;
    for (int i = t; i < 10000; i += 256) s_in[i] = in[b*10000 + i];
    __syncthreads();
    float wA[9], wB[9];
    #pragma unroll
    for (int k = 0; k < 9; k++) { wA[k] = g_c.wA[k]; wB[k] = g_c.wB[k]; }
    float bA = g_c.bA, bB = g_c.bB;

    // stage A into registers
    float r[40];
    #pragma unroll
    for (int rr = 0; rr < 40; rr++) {
        int i = t + rr*256;
        if (i >= 10000) continue;
        int uv = i / 100, hw = i % 100, u = uv / 10, v = uv % 10;
        float a = bA;
        #pragma unroll
        for (int ku = 0; ku < 3; ku++) {
            int u2 = u + ku - 1;
            if (u2 < 0 || u2 >= 10) continue;
            #pragma unroll
            for (int kv = 0; kv < 3; kv++) {
                int v2 = v + kv - 1;
                if (v2 < 0 || v2 >= 10) continue;
                a = fmaf(wA[ku*3 + kv], s_in[(u2*10 + v2)*100 + hw], a);
            }
        }
        r[rr] = fmaxf(a, 0.f);
    }
    __syncthreads();
    #pragma unroll
    for (int rr = 0; rr < 40; rr++) {
        int i = t + rr*256;
        if (i < 10000) s_in[i] = r[rr];
    }
    __syncthreads();

    // stage B from smem -> g_t2[mode]
    float* __restrict__ t2o = g_t2[mode] + (size_t)b*10000;
    for (int i = t; i < 10000; i += 256) {
        int uv = i / 100, hw = i % 100, h = hw / 10, w = hw % 10;
        float a = bB;
        #pragma unroll
        for (int kh = 0; kh < 3; kh++) {
            int h2 = h + kh - 1;
            if (h2 < 0 || h2 >= 10) continue;
            #pragma unroll
            for (int kw = 0; kw < 3; kw++) {
                int w2 = w + kw - 1;
                if (w2 < 0 || w2 >= 10) continue;
                a = fmaf(wB[kh*3 + kw], s_in[uv*100 + h2*10 + w2], a);
            }
        }
        t2o[i] = a;
    }
}

// ---------------- fused stage D+EF ----------------
// D: per point, 16 channels r_j = relu(aC_j*t2 + cC_j); y_o = relu(sum_{tap,j} wD * r_j + tD_o)
// EF: folded 16->1 3x3 conv over (h,w), scattered into shared accumulator.
// grid = (5, BTOT, 2). Occupancy-tuned: __launch_bounds__(256, 2) targets 2 CTA/SM
// (16 warps) to hide LDS/dep latency; aC/cC/tD read via broadcast LDS (saves 48 regs).
__global__ void __launch_bounds__(256, 2) stageDEF_kernel() {
    __shared__ float accs[2000];
    __shared__ ull wDs[2304];
    __shared__ ull wEFs[144];
    __shared__ float aCs[16], cCs[16], tDs[16];
    int qu = blockIdx.x, b = blockIdx.y, mode = blockIdx.z, t = threadIdx.x;
    for (int i = t; i < 2000; i += 256) accs[i] = 0.f;
    for (int i = t; i < 2304; i += 256) wDs[i] = g_wDp[i];
    if (t < 144) wEFs[t] = g_wEFp[t];
    if (t < 16) { aCs[t] = g_c.aC[t]; cCs[t] = g_c.cC[t]; tDs[t] = g_c.tD[t]; }
    __syncthreads();
    const float* __restrict__ t2b = g_t2[mode] + (size_t)b*10000;

    for (int tile = t; tile < 500; tile += 256) {
        int luv = tile / 25;            // 0..19 within fifth
        int hw0 = (tile % 25) * 4;      // 4 consecutive hw points
        int uv  = qu*20 + luv;
        int u = uv / 10, v = uv % 10;

        ull a01[16], a23[16];
        #pragma unroll
        for (int o = 0; o < 16; o++) { a01[o] = 0ull; a23[o] = 0ull; }

        #pragma unroll 1
        for (int tap = 0; tap < 9; tap++) {
            int ua = u + tap/3 - 1, va = v + tap%3 - 1;
            if (ua < 0 || ua >= 10 || va < 0 || va >= 10) continue;  // zero-padded t3
            float4 x4 = *(const float4*)(t2b + (ua*10 + va)*100 + hw0);
            const ull* wt = wDs + tap;
            #pragma unroll
            for (int j = 0; j < 16; j++) {
                float aj = aCs[j], cj = cCs[j];   // broadcast LDS, no register residency
                float r0 = fmaxf(fmaf(aj, x4.x, cj), 0.f);
                float r1 = fmaxf(fmaf(aj, x4.y, cj), 0.f);
                float r2 = fmaxf(fmaf(aj, x4.z, cj), 0.f);
                float r3 = fmaxf(fmaf(aj, x4.w, cj), 0.f);
                ull r01 = pk2(r0, r1), r23 = pk2(r2, r3);
                #pragma unroll
                for (int o = 0; o < 16; o++) {
                    ull w = wt[(o*16 + j)*9];
                    a01[o] = ffma2(w, r01, a01[o]);
                    a23[o] = ffma2(w, r23, a23[o]);
                }
            }
        }

        // EF: t4_o = relu(acc_o + tD_o); sc[tap] = sum_o wEF[tap][o] * t4_o
        ull sc01[9], sc23[9];
        #pragma unroll
        for (int k = 0; k < 9; k++) { sc01[k] = 0ull; sc23[k] = 0ull; }
        #pragma unroll
        for (int o = 0; o < 16; o++) {
            float td = tDs[o];                    // broadcast LDS
            float p0, p1, p2, p3;
            up2(a01[o], p0, p1); up2(a23[o], p2, p3);
            p0 = fmaxf(p0 + td, 0.f);
            p1 = fmaxf(p1 + td, 0.f);
            p2 = fmaxf(p2 + td, 0.f);
            p3 = fmaxf(p3 + td, 0.f);
            ull t01 = pk2(p0, p1), t23 = pk2(p2, p3);
            #pragma unroll
            for (int k = 0; k < 9; k++) {
                ull w = wEFs[k*16 + o];
                sc01[k] = ffma2(w, t01, sc01[k]);
                sc23[k] = ffma2(w, t23, sc23[k]);
            }
        }
        // scatter: t4 at (h,w) with tap (kh,kw) contributes to output (h+1-kh, w+1-kw)
        #pragma unroll 1
        for (int k = 0; k < 9; k++) {
            int dh = 1 - k/3, dw = 1 - k%3;
            float s0, s1, s2, s3;
            up2(sc01[k], s0, s1); up2(sc23[k], s2, s3);
            float sv[4] = {s0, s1, s2, s3};
            #pragma unroll
            for (int p = 0; p < 4; p++) {
                int hw = hw0 + p;
                int h2 = hw/10 + dh, w2 = hw%10 + dw;
                if (h2 >= 0 && h2 < 10 && w2 >= 0 && w2 < 10)
                    atomicAdd(&accs[luv*100 + h2*10 + w2], sv[p]);
            }
        }
    }
    __syncthreads();
    float bEF = g_c.bEF;
    if (mode == 0) {
        for (int i = t; i < 2000; i += 256)
            g_cca1[(size_t)b*10000 + qu*2000 + i] = accs[i] + bEF;
    } else {
        for (int i = t; i < 2000; i += 256) {
            int luv = i / 100, hw = i % 100;
            int uv = qu*20 + luv;
            g_cca2[(size_t)b*10000 + hw*100 + uv] = accs[i] + bEF;  // plain transposed store
        }
    }
}

// ---------------- gaussian-normalize (ddof=1) + softmax(T=5) + sums ----------------
__global__ void __launch_bounds__(128) attn_kernel() {
    __shared__ float s[10000];
    __shared__ float cmean[100], cinv[100], cmax[100], cZi[100];
    __shared__ float rmean[100], rinv[100], rmax[100], rZi[100];
    int b = blockIdx.x, t = threadIdx.x;
    for (int i = t; i < 10000; i += 128)
        s[i] = g_cca1[(size_t)b*10000 + i] + g_cca2[(size_t)b*10000 + i];
    __syncthreads();
    if (t < 100) {
        float sum = 0.f, sq = 0.f, mx = -1e30f;
        for (int ps = 0; ps < 100; ps++) {
            float v = s[ps*100 + t];
            sum += v; sq = fmaf(v, v, sq); mx = fmaxf(mx, v);
        }
        float mean = sum * 0.01f;
        float var  = (sq - sum*mean) * (1.f/99.f);
        float inv  = rsqrtf(var + 1e-5f) * 0.2f;   // includes 1/TEMPERATURE_ATTN
        float Lm   = (mx - mean) * inv;
        float Z = 0.f;
        for (int ps = 0; ps < 100; ps++)
            Z += expf((s[ps*100 + t] - mean)*inv - Lm);
        cmean[t] = mean; cinv[t] = inv; cmax[t] = Lm; cZi[t] = 1.f/Z;

        sum = 0.f; sq = 0.f; mx = -1e30f;
        for (int pq = 0; pq < 100; pq++) {
            float v = s[t*100 + pq];
            sum += v; sq = fmaf(v, v, sq); mx = fmaxf(mx, v);
        }
        mean = sum * 0.01f;
        var  = (sq - sum*mean) * (1.f/99.f);
        inv  = rsqrtf(var + 1e-5f) * 0.2f;
        Lm   = (mx - mean) * inv;
        Z = 0.f;
        for (int pq = 0; pq < 100; pq++)
            Z += expf((s[t*100 + pq] - mean)*inv - Lm);
        rmean[t] = mean; rinv[t] = inv; rmax[t] = Lm; rZi[t] = 1.f/Z;
    }
    __syncthreads();
    if (t < 100) {
        float a = 0.f;
        for (int pq = 0; pq < 100; pq++) {
            float v = s[t*100 + pq];
            a += expf((v - cmean[pq])*cinv[pq] - cmax[pq]) * cZi[pq];
        }
        g_as[b*100 + t] = a;
        float q = 0.f;
        for (int ps = 0; ps < 100; ps++) {
            float v = s[ps*100 + t];
            q += expf((v - rmean[ps])*rinv[ps] - rmax[ps]) * rZi[ps];
        }
        g_aq[b*100 + t] = q;
    }
}

// ---------------- attended pooling + cosine sim ----------------
__global__ void __launch_bounds__(256) final_kernel(
        const float* __restrict__ spt, const float* __restrict__ qry,
        float* __restrict__ out) {
    __shared__ float as[100], aq[100];
    __shared__ float red[256];
    int b = blockIdx.x;
    int qi = b / WAYN, n = b % WAYN;
    int t = threadIdx.x;
    if (t < 100) { as[t] = g_as[b*100 + t]; aq[t] = g_aq[b*100 + t]; }
    __syncthreads();
    float pr = (t < 100) ? as[t]*g_meanC[n*100 + t] : 0.f;
    red[t] = pr; __syncthreads();
    for (int st = 128; st > 0; st >>= 1) { if (t < st) red[t] += red[t + st]; __syncthreads(); }
    float dot_s = red[0]; __syncthreads();
    pr = (t < 100) ? aq[t]*g_meanC[(WAYN + qi)*100 + t] : 0.f;
    red[t] = pr; __syncthreads();
    for (int st = 128; st > 0; st >>= 1) { if (t < st) red[t] += red[t + st]; __syncthreads(); }
    float dot_q = red[0]; __syncthreads();

    float num = 0.f, ss = 0.f, qq = 0.f;
    const float* sp = spt + (size_t)n*CIN*P;
    const float* qp = qry + (size_t)qi*CIN*P;
    for (int c = t; c < CIN; c += 256) {
        const float* srow = sp + c*P;
        const float* qrow = qp + c*P;
        float sa = 0.f, qa = 0.f;
        for (int p = 0; p < P; p++) {
            sa = fmaf(as[p], srow[p], sa);
            qa = fmaf(aq[p], qrow[p], qa);
        }
        sa = (sa - dot_s) * 0.01f;
        qa = (qa - dot_q) * 0.01f;
        num = fmaf(sa, qa, num);
        ss  = fmaf(sa, sa, ss);
        qq  = fmaf(qa, qa, qq);
    }
    red[t] = num; __syncthreads();
    for (int st = 128; st > 0; st >>= 1) { if (t < st) red[t] += red[t + st]; __syncthreads(); }
    float N = red[0]; __syncthreads();
    red[t] = ss; __syncthreads();
    for (int st = 128; st > 0; st >>= 1) { if (t < st) red[t] += red[t + st]; __syncthreads(); }
    float S = red[0]; __syncthreads();
    red[t] = qq; __syncthreads();
    for (int st = 128; st > 0; st >>= 1) { if (t < st) red[t] += red[t + st]; __syncthreads(); }
    float Qv = red[0];
    if (t == 0) {
        float den = fmaxf(sqrtf(S), 1e-8f) * fmaxf(sqrtf(Qv), 1e-8f);
        out[b] = (N / den) * 5.0f;    // /TEMPERATURE (0.2)
    }
}

// ---------------- qry_pooled ----------------
__global__ void __launch_bounds__(128) pooled_kernel(
        const float* __restrict__ qry, float* __restrict__ out) {
    __shared__ float red[128];
    int q = blockIdx.x, t = threadIdx.x;
    red[t] = (t < 100) ? g_meanC[(WAYN + q)*100 + t] : 0.f;
    __syncthreads();
    for (int st = 64; st > 0; st >>= 1) { if (t < st) red[t] += red[t + st]; __syncthreads(); }
    float mp = red[0] * 0.01f;
    const float* qp = qry + (size_t)q*CIN*P;
    for (int c = t; c < CIN; c += 128) {
        float s = 0.f;
        for (int p = 0; p < P; p++) s += qp[c*P + p];
        out[BTOT + q*CIN + c] = s * 0.01f - mp;
    }
}

// ---------------- launcher ----------------
extern "C" void kernel_launch(void* const* d_in, const int* in_sizes, int n_in,
                              void* d_out, int out_size) {
    const float* spt   = (const float*)d_in[0];
    const float* qry   = (const float*)d_in[1];
    const float* w1x1  = (const float*)d_in[2];
    const float* bn1x1 = (const float*)d_in[3];
    const float* c1w2  = (const float*)d_in[4];
    const float* c1b2  = (const float*)d_in[5];
    const float* c1w1  = (const float*)d_in[6];
    const float* c1b1  = (const float*)d_in[7];
    const float* c1pw  = (const float*)d_in[8];
    const float* c1bp  = (const float*)d_in[9];
    const float* c2w2  = (const float*)d_in[10];
    const float* c2b2  = (const float*)d_in[11];
    const float* c2w1  = (const float*)d_in[12];
    const float* c2b1  = (const float*)d_in[13];
    const float* c2pw  = (const float*)d_in[14];
    const float* c2bp  = (const float*)d_in[15];
    float* out = (float*)d_out;

    prep_kernel<<<1, 256>>>(w1x1, bn1x1, c1w2, c1b2, c1w1, c1b1, c1pw, c1bp,
                            c2w2, c2b2, c2w1, c2b1, c2pw, c2bp);
    feat_kernel<<<80, 256>>>(spt, qry, w1x1);
    corr_kernel<<<BTOT, 256>>>();

    stageAB_kernel<<<dim3(BTOT, 2), 256>>>();
    stageDEF_kernel<<<dim3(5, BTOT, 2), 256>>>();

    attn_kernel<<<BTOT, 128>>>();
    final_kernel<<<BTOT, 256>>>(spt, qry, out);
    pooled_kernel<<<QN, 128>>>(qry, out);
}